// round 1
// baseline (speedup 1.0000x reference)
#include <cuda_runtime.h>

// ---------------------------------------------------------------------------
// Fastformer additive attention, fp32 baseline.
// Pipeline:
//   1. g_Q = Q_seq @ WQ                          (GEMM 16384x1024x1024)
//   2. g_K = K_seq @ WK                          (GEMM)
//   3. logA[b,h,s] = (Q[b,s,:]@Wa[:,h]) * 1/8    (small proj)
//   4. poolA: alpha=softmax_s(logA); qg[b,h,j]=sum_s alpha*Q[b,s,h*64+j]
//   5. logB[b,e,s'] via the reshape-scramble gather on K * qg
//   6. poolB: beta=softmax; kg[b,h*64+j]=qg[b,h,j]*sum_s beta*K[b,s,h*64+j]
//   7. out = (Q * kg_broadcast_over_rows) @ WP + Q   (GEMM w/ fused scale+resid)
// ---------------------------------------------------------------------------

#define Bc 8
#define Sc 2048
#define Dc 1024
#define Hc 16
#define DHc 64
#define Mc (Bc * Sc)   // 16384

// scratch (device globals: allocation-free per harness rules)
__device__ float g_Q[Mc * Dc];            // 64 MB
__device__ float g_K[Mc * Dc];            // 64 MB
__device__ float g_logA[Bc * Hc * Sc];
__device__ float g_logB[Bc * Hc * Sc];
__device__ float g_qg[Bc * Hc * DHc];
__device__ float g_kg[Bc * Dc];

// ---------------------------------------------------------------------------
// Tiled SGEMM: C[M,N] = A[M,K] * W[K,N]  (all row-major), M=16384,N=K=1024.
// MODE 0: plain.  MODE 1: A scaled per-K-column by scaleVec[b*Dc+k] (b = row
// batch, constant per 128-row block since 2048 % 128 == 0), epilogue += resid.
// BM=BN=128, BK=16, TM=TN=8, 256 threads.
// ---------------------------------------------------------------------------
template <int MODE>
__global__ __launch_bounds__(256, 2)
void gemm_k(const float* __restrict__ A, const float* __restrict__ W,
            float* __restrict__ C, const float* __restrict__ scaleVec,
            const float* __restrict__ resid)
{
    __shared__ float As[16][128];   // As[k][m]
    __shared__ float Bs[16][128];   // Bs[k][n]

    const int crow = blockIdx.y * 128;
    const int ccol = blockIdx.x * 128;
    const int tid  = threadIdx.x;

    const int aRow = tid >> 2;          // 0..63 (plus +64)
    const int aCol = (tid & 3) * 4;     // 0,4,8,12
    const int bRow = tid >> 5;          // 0..7 (plus +8)
    const int bCol = (tid & 31) * 4;    // 0..124

    const int tr = (tid >> 4) * 8;      // thread tile row
    const int tc = (tid & 15) * 8;      // thread tile col

    const int bb = crow / Sc;           // batch index (MODE 1)

    float acc[8][8];
#pragma unroll
    for (int i = 0; i < 8; i++)
#pragma unroll
        for (int j = 0; j < 8; j++) acc[i][j] = 0.f;

    const float* Ab = A + (size_t)crow * Dc;

    for (int k0 = 0; k0 < Dc; k0 += 16) {
        // load A tile (128x16), transpose into As
#pragma unroll
        for (int i = 0; i < 2; i++) {
            int r = aRow + i * 64;
            float4 v = *reinterpret_cast<const float4*>(Ab + (size_t)r * Dc + k0 + aCol);
            if (MODE == 1) {
                float4 sc = *reinterpret_cast<const float4*>(scaleVec + bb * Dc + k0 + aCol);
                v.x *= sc.x; v.y *= sc.y; v.z *= sc.z; v.w *= sc.w;
            }
            As[aCol + 0][r] = v.x;
            As[aCol + 1][r] = v.y;
            As[aCol + 2][r] = v.z;
            As[aCol + 3][r] = v.w;
        }
        // load W tile (16x128)
#pragma unroll
        for (int i = 0; i < 2; i++) {
            int r = bRow + i * 8;
            float4 v = *reinterpret_cast<const float4*>(W + (size_t)(k0 + r) * Dc + ccol + bCol);
            *reinterpret_cast<float4*>(&Bs[r][bCol]) = v;
        }
        __syncthreads();

#pragma unroll
        for (int k = 0; k < 16; k++) {
            float4 a0 = *reinterpret_cast<const float4*>(&As[k][tr]);
            float4 a1 = *reinterpret_cast<const float4*>(&As[k][tr + 4]);
            float4 b0 = *reinterpret_cast<const float4*>(&Bs[k][tc]);
            float4 b1 = *reinterpret_cast<const float4*>(&Bs[k][tc + 4]);
            float ra[8] = {a0.x, a0.y, a0.z, a0.w, a1.x, a1.y, a1.z, a1.w};
            float rb[8] = {b0.x, b0.y, b0.z, b0.w, b1.x, b1.y, b1.z, b1.w};
#pragma unroll
            for (int i = 0; i < 8; i++)
#pragma unroll
                for (int j = 0; j < 8; j++) acc[i][j] += ra[i] * rb[j];
        }
        __syncthreads();
    }

    // epilogue
#pragma unroll
    for (int i = 0; i < 8; i++) {
        int r = crow + tr + i;
#pragma unroll
        for (int j = 0; j < 8; j += 4) {
            float4 v = make_float4(acc[i][j], acc[i][j + 1], acc[i][j + 2], acc[i][j + 3]);
            if (MODE == 1) {
                float4 q = *reinterpret_cast<const float4*>(resid + (size_t)r * Dc + ccol + tc + j);
                v.x += q.x; v.y += q.y; v.z += q.z; v.w += q.w;
            }
            *reinterpret_cast<float4*>(C + (size_t)r * Dc + ccol + tc + j) = v;
        }
    }
}

// ---------------------------------------------------------------------------
// logitsA: one warp per (b,s). logA[b,e,s] = 0.125 * sum_d Q[b,s,d]*Wa[d,e]
// ---------------------------------------------------------------------------
__global__ void logitsA_k(const float* __restrict__ Wa)
{
    int gw = (blockIdx.x * blockDim.x + threadIdx.x) >> 5;
    if (gw >= Mc) return;
    int lane = threadIdx.x & 31;
    int b = gw >> 11;       // /2048
    int s = gw & 2047;

    const float* q = g_Q + (size_t)gw * Dc;
    float acc[16];
#pragma unroll
    for (int e = 0; e < 16; e++) acc[e] = 0.f;

    for (int d = lane; d < Dc; d += 32) {
        float qv = q[d];
        const float4* w4 = reinterpret_cast<const float4*>(Wa + d * 16);
        float4 w0 = w4[0], w1 = w4[1], w2 = w4[2], w3 = w4[3];
        acc[0]  += qv * w0.x; acc[1]  += qv * w0.y; acc[2]  += qv * w0.z; acc[3]  += qv * w0.w;
        acc[4]  += qv * w1.x; acc[5]  += qv * w1.y; acc[6]  += qv * w1.z; acc[7]  += qv * w1.w;
        acc[8]  += qv * w2.x; acc[9]  += qv * w2.y; acc[10] += qv * w2.z; acc[11] += qv * w2.w;
        acc[12] += qv * w3.x; acc[13] += qv * w3.y; acc[14] += qv * w3.z; acc[15] += qv * w3.w;
    }
#pragma unroll
    for (int e = 0; e < 16; e++) {
        float v = acc[e];
#pragma unroll
        for (int o = 16; o; o >>= 1) v += __shfl_xor_sync(0xffffffffu, v, o);
        if (lane == e) g_logA[(b * Hc + e) * Sc + s] = v * 0.125f;
    }
}

// ---------------------------------------------------------------------------
// logitsB: one warp per (b,s'). Uses the reshape-scramble mapping:
//   h0 = s'/128, s0 = (s' mod 128)*16
//   logB[b,e,s'] = 0.125 * sum_{k<1024} K[b, s0+k/64, h0*64 + k%64]
//                                     * qg[b,h0,k%64] * Wb[k,e]
// ---------------------------------------------------------------------------
__global__ void logitsB_k(const float* __restrict__ Wb)
{
    int gw = (blockIdx.x * blockDim.x + threadIdx.x) >> 5;
    if (gw >= Mc) return;
    int lane = threadIdx.x & 31;
    int b  = gw >> 11;
    int sp = gw & 2047;
    int h0 = sp >> 7;
    int s0 = (sp & 127) << 4;

    const float* qgv = g_qg + (b * Hc + h0) * DHc;
    const float* Kb  = g_K + ((size_t)(b * Sc + s0)) * Dc + h0 * DHc;

    float acc[16];
#pragma unroll
    for (int e = 0; e < 16; e++) acc[e] = 0.f;

    for (int k = lane; k < Dc; k += 32) {
        int t = k >> 6, j = k & 63;
        float v = Kb[(size_t)t * Dc + j] * qgv[j];
        const float4* w4 = reinterpret_cast<const float4*>(Wb + k * 16);
        float4 w0 = w4[0], w1 = w4[1], w2 = w4[2], w3 = w4[3];
        acc[0]  += v * w0.x; acc[1]  += v * w0.y; acc[2]  += v * w0.z; acc[3]  += v * w0.w;
        acc[4]  += v * w1.x; acc[5]  += v * w1.y; acc[6]  += v * w1.z; acc[7]  += v * w1.w;
        acc[8]  += v * w2.x; acc[9]  += v * w2.y; acc[10] += v * w2.z; acc[11] += v * w2.w;
        acc[12] += v * w3.x; acc[13] += v * w3.y; acc[14] += v * w3.z; acc[15] += v * w3.w;
    }
#pragma unroll
    for (int e = 0; e < 16; e++) {
        float v = acc[e];
#pragma unroll
        for (int o = 16; o; o >>= 1) v += __shfl_xor_sync(0xffffffffu, v, o);
        if (lane == e) g_logB[(b * Hc + e) * Sc + sp] = v * 0.125f;
    }
}

// ---------------------------------------------------------------------------
// pool: one block per (b,h). softmax over S logits, then weighted reduction of
// X[b, :, h*64+j]. If qscale != null, multiply by qscale (poolB path).
// out index (b*H+h)*64+j  (== b*Dc + h*64 + j since Dc = H*64).
// ---------------------------------------------------------------------------
__global__ void pool_k(const float* __restrict__ logits, const float* __restrict__ X,
                       const float* __restrict__ qscale, float* __restrict__ out)
{
    int bh = blockIdx.x;
    int b = bh >> 4, h = bh & 15;
    const float* lg = logits + bh * Sc;

    __shared__ float sE[Sc];
    __shared__ float red[8];
    __shared__ float part[4][DHc];

    int tid = threadIdx.x;

    // max
    float mx = -1e30f;
    for (int s = tid; s < Sc; s += 256) mx = fmaxf(mx, lg[s]);
#pragma unroll
    for (int o = 16; o; o >>= 1) mx = fmaxf(mx, __shfl_xor_sync(0xffffffffu, mx, o));
    if ((tid & 31) == 0) red[tid >> 5] = mx;
    __syncthreads();
    float m8 = red[tid & 7];
#pragma unroll
    for (int o = 4; o; o >>= 1) m8 = fmaxf(m8, __shfl_xor_sync(0xffffffffu, m8, o));
    mx = m8;
    __syncthreads();

    // exp + sum
    float sum = 0.f;
    for (int s = tid; s < Sc; s += 256) {
        float e = __expf(lg[s] - mx);
        sE[s] = e;
        sum += e;
    }
#pragma unroll
    for (int o = 16; o; o >>= 1) sum += __shfl_xor_sync(0xffffffffu, sum, o);
    if ((tid & 31) == 0) red[tid >> 5] = sum;
    __syncthreads();
    float tot = 0.f;
#pragma unroll
    for (int i = 0; i < 8; i++) tot += red[i];
    float inv = 1.0f / tot;

    // weighted pooling
    int j = tid & 63, g = tid >> 6;
    const float* Xb = X + ((size_t)b * Sc) * Dc + h * DHc + j;
    float acc = 0.f;
    for (int s = g; s < Sc; s += 4) acc += sE[s] * Xb[(size_t)s * Dc];
    part[g][j] = acc;
    __syncthreads();
    if (g == 0) {
        float v = (part[0][j] + part[1][j] + part[2][j] + part[3][j]) * inv;
        if (qscale) v *= qscale[bh * DHc + j];
        out[bh * DHc + j] = v;
    }
}

// ---------------------------------------------------------------------------
extern "C" void kernel_launch(void* const* d_in, const int* in_sizes, int n_in,
                              void* d_out, int out_size)
{
    const float* Qseq = (const float*)d_in[0];
    const float* Kseq = (const float*)d_in[1];
    // d_in[2] = V_seq, unused by the reference
    const float* WQ = (const float*)d_in[3];
    const float* WK = (const float*)d_in[4];
    const float* Wa = (const float*)d_in[5];
    const float* Wb = (const float*)d_in[6];
    const float* WP = (const float*)d_in[7];
    float* out = (float*)d_out;

    float *pQ, *pK, *pLA, *pLB, *pqg, *pkg;
    cudaGetSymbolAddress((void**)&pQ,  g_Q);
    cudaGetSymbolAddress((void**)&pK,  g_K);
    cudaGetSymbolAddress((void**)&pLA, g_logA);
    cudaGetSymbolAddress((void**)&pLB, g_logB);
    cudaGetSymbolAddress((void**)&pqg, g_qg);
    cudaGetSymbolAddress((void**)&pkg, g_kg);

    dim3 gg(Dc / 128, Mc / 128);   // (8, 128)

    gemm_k<0><<<gg, 256>>>(Qseq, WQ, pQ, nullptr, nullptr);
    gemm_k<0><<<gg, 256>>>(Kseq, WK, pK, nullptr, nullptr);
    logitsA_k<<<Mc / 8, 256>>>(Wa);
    pool_k<<<Bc * Hc, 256>>>(pLA, pQ, nullptr, pqg);
    logitsB_k<<<Mc / 8, 256>>>(Wb);
    pool_k<<<Bc * Hc, 256>>>(pLB, pK, pqg, pkg);
    gemm_k<1><<<gg, 256>>>(pQ, WP, out, pkg, pQ);
}

// round 3
// speedup vs baseline: 3.8260x; 3.8260x over previous
#include <cuda_runtime.h>
#include <cstdint>

// ---------------------------------------------------------------------------
// Fastformer additive attention — tf32 mma.sync GEMMs (compute_103-safe).
// ---------------------------------------------------------------------------

#define Bc 8
#define Sc 2048
#define Dc 1024
#define Hc 16
#define DHc 64
#define Mc (Bc * Sc)   // 16384

// scratch (device globals)
__device__ float g_Q[Mc * Dc];         // GEMM1 out fp32
__device__ float g_K[Mc * Dc];         // GEMM2 out fp32
__device__ float g_Qtf[Mc * Dc];       // GEMM1 out, tf32-rounded (GEMM3 A operand)
__device__ float g_Qseq_tf[Mc * Dc];   // tf32-rounded inputs
__device__ float g_Kseq_tf[Mc * Dc];
__device__ float g_WQt[Dc * Dc];       // tf32-rounded weights (K-major as given)
__device__ float g_WKt[Dc * Dc];
__device__ float g_WP8[Bc * Dc * Dc];  // per-batch kg-scaled, tf32-rounded WP
__device__ float g_logA[Bc * Hc * Sc];
__device__ float g_logB[Bc * Hc * Sc];
__device__ float g_qg[Bc * Hc * DHc];
__device__ float g_kg[Bc * Dc];

// ===========================================================================
// helpers
// ===========================================================================
__device__ __forceinline__ uint32_t cvta_smem(const void* p) {
    uint32_t a;
    asm("{ .reg .u64 t; cvta.to.shared.u64 t, %1; cvt.u32.u64 %0, t; }" : "=r"(a) : "l"(p));
    return a;
}
__device__ __forceinline__ uint32_t f2tf(float x) {
    uint32_t u;
    asm("cvt.rna.tf32.f32 %0, %1;" : "=r"(u) : "f"(x));
    return u;
}
__device__ __forceinline__ float tff(float x) { return __uint_as_float(f2tf(x)); }

__device__ __forceinline__ void cp16(uint32_t s, const void* g) {
    asm volatile("cp.async.cg.shared.global [%0], [%1], 16;" :: "r"(s), "l"(g));
}
__device__ __forceinline__ void cp_commit() {
    asm volatile("cp.async.commit_group;" ::: "memory");
}
template <int N>
__device__ __forceinline__ void cp_wait() {
    asm volatile("cp.async.wait_group %0;" :: "n"(N) : "memory");
}
__device__ __forceinline__ void mma_tf32(float& c0, float& c1, float& c2, float& c3,
                                         uint32_t a0, uint32_t a1, uint32_t a2, uint32_t a3,
                                         uint32_t b0, uint32_t b1) {
    asm volatile(
        "mma.sync.aligned.m16n8k8.row.col.f32.tf32.tf32.f32 "
        "{%0,%1,%2,%3}, {%4,%5,%6,%7}, {%8,%9}, {%0,%1,%2,%3};"
        : "+f"(c0), "+f"(c1), "+f"(c2), "+f"(c3)
        : "r"(a0), "r"(a1), "r"(a2), "r"(a3), "r"(b0), "r"(b1));
}

// ===========================================================================
// tf32 tensor-core GEMM: C[M,N] = A[M,K] @ B[K,N]   (A,B pre-rounded to tf32)
// BM=BN=128, BK=32, 256 threads (8 warps, 2x4), 3-stage cp.async pipeline.
// MODE 0: store C.  MODE 1: store C and Ctf (tf32-rounded copy).
// MODE 2: B indexed per-batch (Bw + bb*Dc*Dc), epilogue adds resid.
// ===========================================================================
#define ASTRIDE 36            // floats per A smem row (32 + 4 pad)
#define BSTRIDE 136           // floats per B smem row (128 + 8 pad)
#define ABYTES (128 * ASTRIDE * 4)   // 18432
#define BBYTES (32 * BSTRIDE * 4)    // 17408
#define STGB (ABYTES + BBYTES)       // 35840
#define NSTAGE 3
#define GSMEM (NSTAGE * STGB)        // 107520
#define NCH (Dc / 32)                // 32 k-chunks

template <int MODE>
__global__ __launch_bounds__(256, 2)
void gemm_mma(const float* __restrict__ A, const float* __restrict__ Bw,
              float* __restrict__ C, float* __restrict__ Ctf,
              const float* __restrict__ resid)
{
    extern __shared__ char smem[];
    const uint32_t sb = cvta_smem(smem);
    const int tid  = threadIdx.x;
    const int wid  = tid >> 5, lane = tid & 31;
    const int g    = lane >> 2, t = lane & 3;
    const int wm   = wid >> 2, wn = wid & 3;       // warp grid 2(M) x 4(N)
    const int crow = blockIdx.y * 128, ccol = blockIdx.x * 128;

    if (MODE == 2) Bw += (size_t)(crow / Sc) * Dc * Dc;

    // gmem->smem mapping
    const int arow = tid >> 1, ahalf = tid & 1;    // A: 2 thr/row, 4x16B each
    const int brow = tid >> 3, bseg = tid & 7;     // B: 8 thr/row, 4x16B each
    const float* Ag = A + (size_t)(crow + arow) * Dc + ahalf * 16;
    const float* Bg = Bw + (size_t)brow * Dc + ccol + bseg * 4;
    const uint32_t sA = arow * 144 + ahalf * 64;   // bytes
    const uint32_t sB = brow * 544 + bseg * 16;

    float acc[4][4][4];
#pragma unroll
    for (int i = 0; i < 4; i++)
#pragma unroll
        for (int j = 0; j < 4; j++)
#pragma unroll
            for (int k = 0; k < 4; k++) acc[i][j][k] = 0.f;

    auto issue = [&](int c) {
        uint32_t base = sb + (uint32_t)(c % NSTAGE) * STGB;
        const float* ag = Ag + c * 32;
#pragma unroll
        for (int j = 0; j < 4; j++) cp16(base + sA + j * 16, ag + j * 4);
        const float* bg = Bg + (size_t)c * 32 * Dc;
        uint32_t bbase = base + ABYTES;
#pragma unroll
        for (int j = 0; j < 4; j++) cp16(bbase + sB + j * 128, bg + (size_t)j * 32);
        cp_commit();
    };

    issue(0);
    issue(1);

    for (int c = 0; c < NCH; c++) {
        if (c + 2 < NCH) cp_wait<1>(); else cp_wait<0>();
        __syncthreads();
        if (c + 2 < NCH) issue(c + 2);

        const float* As = (const float*)(smem + (c % NSTAGE) * STGB);
        const float* Bs = (const float*)(smem + (c % NSTAGE) * STGB + ABYTES);

#pragma unroll
        for (int kk = 0; kk < 4; kk++) {
            const int k0 = kk * 8;
            uint32_t a[4][4], b[4][2];
#pragma unroll
            for (int im = 0; im < 4; im++) {
                const float* ap = As + (wm * 64 + im * 16 + g) * ASTRIDE + k0 + t;
                a[im][0] = __float_as_uint(ap[0]);
                a[im][1] = __float_as_uint(ap[8 * ASTRIDE]);
                a[im][2] = __float_as_uint(ap[4]);
                a[im][3] = __float_as_uint(ap[8 * ASTRIDE + 4]);
            }
#pragma unroll
            for (int in = 0; in < 4; in++) {
                const float* bp = Bs + (k0 + t) * BSTRIDE + wn * 32 + in * 8 + g;
                b[in][0] = __float_as_uint(bp[0]);
                b[in][1] = __float_as_uint(bp[4 * BSTRIDE]);
            }
#pragma unroll
            for (int im = 0; im < 4; im++)
#pragma unroll
                for (int in = 0; in < 4; in++)
                    mma_tf32(acc[im][in][0], acc[im][in][1], acc[im][in][2], acc[im][in][3],
                             a[im][0], a[im][1], a[im][2], a[im][3],
                             b[in][0], b[in][1]);
        }
        __syncthreads();
    }

    // epilogue
#pragma unroll
    for (int im = 0; im < 4; im++) {
#pragma unroll
        for (int in = 0; in < 4; in++) {
            const int r0 = crow + wm * 64 + im * 16 + g;
            const int cc = ccol + wn * 32 + in * 8 + 2 * t;
            float2 v0 = make_float2(acc[im][in][0], acc[im][in][1]);
            float2 v1 = make_float2(acc[im][in][2], acc[im][in][3]);
            if (MODE == 2) {
                float2 q0 = *(const float2*)(resid + (size_t)r0 * Dc + cc);
                float2 q1 = *(const float2*)(resid + (size_t)(r0 + 8) * Dc + cc);
                v0.x += q0.x; v0.y += q0.y; v1.x += q1.x; v1.y += q1.y;
            }
            *(float2*)(C + (size_t)r0 * Dc + cc) = v0;
            *(float2*)(C + (size_t)(r0 + 8) * Dc + cc) = v1;
            if (MODE == 1) {
                *(float2*)(Ctf + (size_t)r0 * Dc + cc) = make_float2(tff(v0.x), tff(v0.y));
                *(float2*)(Ctf + (size_t)(r0 + 8) * Dc + cc) = make_float2(tff(v1.x), tff(v1.y));
            }
        }
    }
}

// ===========================================================================
// elementwise tf32 rounding (float4)
// ===========================================================================
__global__ void cvt_tf32_k(const float* __restrict__ in, float* __restrict__ out, int n4)
{
    int i = blockIdx.x * blockDim.x + threadIdx.x;
    if (i >= n4) return;
    float4 v = ((const float4*)in)[i];
    v.x = tff(v.x); v.y = tff(v.y); v.z = tff(v.z); v.w = tff(v.w);
    ((float4*)out)[i] = v;
}

// per-batch scaled WP: g_WP8[b][k][n] = rna(kg[b,k] * WP[k][n])
__global__ void wp8_k(const float* __restrict__ WP)
{
    int i = blockIdx.x * 256 + threadIdx.x;    // over 8*1024*256 float4s
    int n4 = i & 255, k = (i >> 8) & 1023, b = i >> 18;
    float s = g_kg[b * Dc + k];
    float4 w = ((const float4*)WP)[k * 256 + n4];
    w.x = tff(w.x * s); w.y = tff(w.y * s); w.z = tff(w.z * s); w.w = tff(w.w * s);
    ((float4*)g_WP8)[((size_t)b << 18) + k * 256 + n4] = w;
}

// ===========================================================================
// logitsA: one warp per (b,s). logA[b,e,s] = 0.125 * sum_d Q[b,s,d]*Wa[d,e]
// ===========================================================================
__global__ void logitsA_k(const float* __restrict__ Wa)
{
    int gw = (blockIdx.x * blockDim.x + threadIdx.x) >> 5;
    if (gw >= Mc) return;
    int lane = threadIdx.x & 31;
    int b = gw >> 11, s = gw & 2047;

    const float* q = g_Q + (size_t)gw * Dc;
    float acc[16];
#pragma unroll
    for (int e = 0; e < 16; e++) acc[e] = 0.f;

    for (int d = lane; d < Dc; d += 32) {
        float qv = q[d];
        const float4* w4 = reinterpret_cast<const float4*>(Wa + d * 16);
        float4 w0 = w4[0], w1 = w4[1], w2 = w4[2], w3 = w4[3];
        acc[0]  += qv * w0.x; acc[1]  += qv * w0.y; acc[2]  += qv * w0.z; acc[3]  += qv * w0.w;
        acc[4]  += qv * w1.x; acc[5]  += qv * w1.y; acc[6]  += qv * w1.z; acc[7]  += qv * w1.w;
        acc[8]  += qv * w2.x; acc[9]  += qv * w2.y; acc[10] += qv * w2.z; acc[11] += qv * w2.w;
        acc[12] += qv * w3.x; acc[13] += qv * w3.y; acc[14] += qv * w3.z; acc[15] += qv * w3.w;
    }
#pragma unroll
    for (int e = 0; e < 16; e++) {
        float v = acc[e];
#pragma unroll
        for (int o = 16; o; o >>= 1) v += __shfl_xor_sync(0xffffffffu, v, o);
        if (lane == e) g_logA[(b * Hc + e) * Sc + s] = v * 0.125f;
    }
}

// ===========================================================================
// logitsB: reshape-scramble gather path
// ===========================================================================
__global__ void logitsB_k(const float* __restrict__ Wb)
{
    int gw = (blockIdx.x * blockDim.x + threadIdx.x) >> 5;
    if (gw >= Mc) return;
    int lane = threadIdx.x & 31;
    int b = gw >> 11, sp = gw & 2047;
    int h0 = sp >> 7, s0 = (sp & 127) << 4;

    const float* qgv = g_qg + (b * Hc + h0) * DHc;
    const float* Kb  = g_K + ((size_t)(b * Sc + s0)) * Dc + h0 * DHc;

    float acc[16];
#pragma unroll
    for (int e = 0; e < 16; e++) acc[e] = 0.f;

    for (int k = lane; k < Dc; k += 32) {
        int tt = k >> 6, j = k & 63;
        float v = Kb[(size_t)tt * Dc + j] * qgv[j];
        const float4* w4 = reinterpret_cast<const float4*>(Wb + k * 16);
        float4 w0 = w4[0], w1 = w4[1], w2 = w4[2], w3 = w4[3];
        acc[0]  += v * w0.x; acc[1]  += v * w0.y; acc[2]  += v * w0.z; acc[3]  += v * w0.w;
        acc[4]  += v * w1.x; acc[5]  += v * w1.y; acc[6]  += v * w1.z; acc[7]  += v * w1.w;
        acc[8]  += v * w2.x; acc[9]  += v * w2.y; acc[10] += v * w2.z; acc[11] += v * w2.w;
        acc[12] += v * w3.x; acc[13] += v * w3.y; acc[14] += v * w3.z; acc[15] += v * w3.w;
    }
#pragma unroll
    for (int e = 0; e < 16; e++) {
        float v = acc[e];
#pragma unroll
        for (int o = 16; o; o >>= 1) v += __shfl_xor_sync(0xffffffffu, v, o);
        if (lane == e) g_logB[(b * Hc + e) * Sc + sp] = v * 0.125f;
    }
}

// ===========================================================================
// pool: one block (512 thr) per (b,h). softmax over S, weighted pooling.
// ===========================================================================
__global__ void pool_k(const float* __restrict__ logits, const float* __restrict__ X,
                       const float* __restrict__ qscale, float* __restrict__ out)
{
    int bh = blockIdx.x;
    int b = bh >> 4, h = bh & 15;
    const float* lg = logits + bh * Sc;

    __shared__ float sE[Sc];
    __shared__ float red[16];
    __shared__ float part[8][DHc];

    int tid = threadIdx.x, lane = tid & 31, warp = tid >> 5;

    float mx = -1e30f;
    for (int s = tid; s < Sc; s += 512) mx = fmaxf(mx, lg[s]);
#pragma unroll
    for (int o = 16; o; o >>= 1) mx = fmaxf(mx, __shfl_xor_sync(0xffffffffu, mx, o));
    if (lane == 0) red[warp] = mx;
    __syncthreads();
    mx = red[0];
#pragma unroll
    for (int i = 1; i < 16; i++) mx = fmaxf(mx, red[i]);
    __syncthreads();

    float sum = 0.f;
    for (int s = tid; s < Sc; s += 512) {
        float e = __expf(lg[s] - mx);
        sE[s] = e;
        sum += e;
    }
#pragma unroll
    for (int o = 16; o; o >>= 1) sum += __shfl_xor_sync(0xffffffffu, sum, o);
    if (lane == 0) red[warp] = sum;
    __syncthreads();
    float tot = 0.f;
#pragma unroll
    for (int i = 0; i < 16; i++) tot += red[i];
    float inv = 1.0f / tot;

    int j = tid & 63, gg = tid >> 6;
    const float* Xb = X + ((size_t)b * Sc) * Dc + h * DHc + j;
    float a0 = 0.f, a1 = 0.f, a2 = 0.f, a3 = 0.f;
    for (int s = gg; s < Sc; s += 32) {
        a0 += sE[s]      * Xb[(size_t)s * Dc];
        a1 += sE[s + 8]  * Xb[(size_t)(s + 8)  * Dc];
        a2 += sE[s + 16] * Xb[(size_t)(s + 16) * Dc];
        a3 += sE[s + 24] * Xb[(size_t)(s + 24) * Dc];
    }
    part[gg][j] = (a0 + a1) + (a2 + a3);
    __syncthreads();
    if (gg == 0) {
        float v = 0.f;
#pragma unroll
        for (int i = 0; i < 8; i++) v += part[i][j];
        v *= inv;
        if (qscale) v *= qscale[bh * DHc + j];
        out[bh * DHc + j] = v;
    }
}

// ===========================================================================
extern "C" void kernel_launch(void* const* d_in, const int* in_sizes, int n_in,
                              void* d_out, int out_size)
{
    const float* Qseq = (const float*)d_in[0];
    const float* Kseq = (const float*)d_in[1];
    // d_in[2] = V_seq, unused by the reference
    const float* WQ = (const float*)d_in[3];
    const float* WK = (const float*)d_in[4];
    const float* Wa = (const float*)d_in[5];
    const float* Wb = (const float*)d_in[6];
    const float* WP = (const float*)d_in[7];
    float* out = (float*)d_out;

    float *pQ, *pK, *pQtf, *pQs, *pKs, *pWQ, *pWK, *pWP8, *pLA, *pLB, *pqg, *pkg;
    cudaGetSymbolAddress((void**)&pQ,   g_Q);
    cudaGetSymbolAddress((void**)&pK,   g_K);
    cudaGetSymbolAddress((void**)&pQtf, g_Qtf);
    cudaGetSymbolAddress((void**)&pQs,  g_Qseq_tf);
    cudaGetSymbolAddress((void**)&pKs,  g_Kseq_tf);
    cudaGetSymbolAddress((void**)&pWQ,  g_WQt);
    cudaGetSymbolAddress((void**)&pWK,  g_WKt);
    cudaGetSymbolAddress((void**)&pWP8, g_WP8);
    cudaGetSymbolAddress((void**)&pLA,  g_logA);
    cudaGetSymbolAddress((void**)&pLB,  g_logB);
    cudaGetSymbolAddress((void**)&pqg,  g_qg);
    cudaGetSymbolAddress((void**)&pkg,  g_kg);

    cudaFuncSetAttribute(gemm_mma<0>, cudaFuncAttributeMaxDynamicSharedMemorySize, GSMEM);
    cudaFuncSetAttribute(gemm_mma<1>, cudaFuncAttributeMaxDynamicSharedMemorySize, GSMEM);
    cudaFuncSetAttribute(gemm_mma<2>, cudaFuncAttributeMaxDynamicSharedMemorySize, GSMEM);

    const int big4 = Mc * Dc / 4;     // 4M float4
    const int w4   = Dc * Dc / 4;     // 256K float4
    cvt_tf32_k<<<(big4 + 255) / 256, 256>>>(Qseq, pQs, big4);
    cvt_tf32_k<<<(big4 + 255) / 256, 256>>>(Kseq, pKs, big4);
    cvt_tf32_k<<<(w4 + 255) / 256, 256>>>(WQ, pWQ, w4);
    cvt_tf32_k<<<(w4 + 255) / 256, 256>>>(WK, pWK, w4);

    dim3 gg(Dc / 128, Mc / 128);      // (8, 128)
    gemm_mma<1><<<gg, 256, GSMEM>>>(pQs, pWQ, pQ, pQtf, nullptr);
    gemm_mma<0><<<gg, 256, GSMEM>>>(pKs, pWK, pK, nullptr, nullptr);

    logitsA_k<<<Mc / 8, 256>>>(Wa);
    pool_k<<<Bc * Hc, 512>>>(pLA, pQ, nullptr, pqg);
    logitsB_k<<<Mc / 8, 256>>>(Wb);
    pool_k<<<Bc * Hc, 512>>>(pLB, pK, pqg, pkg);

    wp8_k<<<Bc * Dc * 256 / 256, 256>>>(WP);
    gemm_mma<2><<<gg, 256, GSMEM>>>(pQtf, pWP8, out, nullptr, pQ);
}